// round 11
// baseline (speedup 1.0000x reference)
#include <cuda_runtime.h>
#include <cuda_bf16.h>
#include <math.h>
#include <stdint.h>

// ---------------- constants ----------------
constexpr int NWIN = 32;
constexpr int NQ = 360;
constexpr int NKP = 1472;          // compacted+padded keys = 23 * 64
constexpr int NKT = 23;            // key tiles
constexpr int TOK = 11520;
constexpr int MTOT = TOK + 256;    // tokens + pooled rows (11776 = 92*128)
constexpr int FFN = 1960;
constexpr int Cch = 512;
constexpr float SC2 = 0.08838834764831845f * 1.4426950408889634f; // qscale * log2(e)

typedef __nv_bfloat16 bf16;
typedef __nv_bfloat162 bf162;

// ---------------- scratch ----------------
__device__ bf16  g_xn[MTOT * Cch];
__device__ bf16  g_qkv[MTOT * 3 * Cch];
__device__ bf16  g_Aw[TOK * Cch];
__device__ float g_xres[TOK * Cch];
__device__ bf16  g_hb[TOK * FFN];
__device__ float g_I[16 * 40 * 60 * 108];
__device__ int   g_valid[120];
__device__ int   g_qidx[NWIN * NQ];
__device__ int   g_kidx[NWIN * NKP];
__device__ bf16  g_wb[3055616];
constexpr int WO_PROJ = 786432;
constexpr int WO_W1   = 1048576;
constexpr int WO_W2   = 2052096;
constexpr int WTOT    = 3055616;

// ---------------- init valid-rolled table ----------------
__global__ void initvalid_k() {
    if (threadIdx.x == 0 && blockIdx.x == 0) {
        int n = 0;
        for (int s = 0; s < 4; s++)
            for (int ih = 0; ih < 5; ih++)
                for (int iw = 0; iw < 9; iw++) {
                    bool zero;
                    if (s == 0) zero = (ih < 3 && iw < 5);
                    else if (s == 1) zero = (ih < 3 && iw >= 4);
                    else if (s == 2) zero = (ih >= 2 && iw < 5);
                    else zero = (ih >= 2 && iw >= 4);
                    if (!zero) g_valid[n++] = s * 45 + ih * 9 + iw;
                }
    }
}

// ---------------- build gather index tables ----------------
__global__ __launch_bounds__(256) void idx_k(int* __restrict__ qidx,
                                             int* __restrict__ kidx) {
    int i = blockIdx.x * 256 + threadIdx.x;
    if (i < NWIN * NQ) {
        int win = i / NQ, q = i - win * NQ;
        int b = win >> 4, wh = (win >> 2) & 3, ww = win & 3;
        int t = q / 45, a = q - t * 45, ih = a / 9, iw = a % 9;
        qidx[i] = ((b * 8 + t) * 20 + wh * 5 + ih) * 36 + ww * 9 + iw;
    }
    if (i < NWIN * NKP) {
        int win = i / NKP, j = i - win * NKP;
        int b = win >> 4, wh = (win >> 2) & 3, ww = win & 3;
        int e = -1;
        if (j < 360) {
            int t = j / 45, a = j - t * 45, ih = a / 9, iw = a % 9;
            e = ((b * 8 + t) * 20 + wh * 5 + ih) * 36 + ww * 9 + iw;
        } else if (j < 1320) {
            int jj = j - 360;
            int t = jj / 120, vi = jj - t * 120;
            int f = g_valid[vi];
            int s = f / 45, a = f - s * 45, ih = a / 9, iw = a % 9;
            int sh = (s < 2) ? -2 : 2;
            int sw = (s & 1) ? 4 : -4;
            int hh = wh * 5 + ih - sh; hh %= 20; if (hh < 0) hh += 20;
            int wp = ww * 9 + iw - sw; wp %= 36; if (wp < 0) wp += 36;
            e = ((b * 8 + t) * 20 + hh) * 36 + wp;
        } else {
            int pos = j - 1320;
            int i0 = (2 - wh) > 0 ? (2 - wh) : 0;
            int iend = (6 - wh) < 5 ? (6 - wh) : 5;
            int rows = iend - i0;
            int nv = rows * 4;
            if (pos < nv * 8) {
                int t = pos / nv, r = pos - t * nv;
                int di = r >> 2, dj = r & 3;
                int gi = wh + (i0 + di) - 2;
                int gj = dj;
                e = TOK + (b * 8 + t) * 16 + gi * 4 + gj;
            }
        }
        kidx[i] = e;
    }
}

// ---------------- all weights fp32 -> bf16 ----------------
__global__ __launch_bounds__(256) void convw_all(const float* __restrict__ a,
                                                 const float* __restrict__ b,
                                                 const float* __restrict__ c,
                                                 const float* __restrict__ d,
                                                 bf16* __restrict__ o) {
    int i4 = (blockIdx.x * 256 + threadIdx.x) * 4;
    if (i4 >= WTOT) return;
    const float* src;
    int off;
    if (i4 < WO_PROJ)      { src = a; off = i4; }
    else if (i4 < WO_W1)   { src = b; off = i4 - WO_PROJ; }
    else if (i4 < WO_W2)   { src = c; off = i4 - WO_W1; }
    else                   { src = d; off = i4 - WO_W2; }
    float4 v = *(const float4*)(src + off);
    *(bf162*)(o + i4)     = __floats2bfloat162_rn(v.x, v.y);
    *(bf162*)(o + i4 + 2) = __floats2bfloat162_rn(v.z, v.w);
}

// ---------------- LayerNorm: 2 rows per warp ----------------
__global__ __launch_bounds__(256) void ln_k(const float* __restrict__ in,
                                            const float* __restrict__ g,
                                            const float* __restrict__ b,
                                            bf16* __restrict__ out) {
    int warp = threadIdx.x >> 5, lane = threadIdx.x & 31;
    int row0 = blockIdx.x * 16 + warp * 2;
    const float4* x0 = (const float4*)(in + (long long)row0 * 512);
    const float4* x1 = (const float4*)(in + (long long)(row0 + 1) * 512);
    float4 v0[4], v1[4];
    float s0 = 0.f, s1 = 0.f;
    #pragma unroll
    for (int i = 0; i < 4; i++) {
        v0[i] = x0[lane + 32 * i];
        v1[i] = x1[lane + 32 * i];
        s0 += v0[i].x + v0[i].y + v0[i].z + v0[i].w;
        s1 += v1[i].x + v1[i].y + v1[i].z + v1[i].w;
    }
    #pragma unroll
    for (int o = 16; o; o >>= 1) {
        s0 += __shfl_xor_sync(0xffffffffu, s0, o);
        s1 += __shfl_xor_sync(0xffffffffu, s1, o);
    }
    float mu0 = s0 * (1.f / 512.f), mu1 = s1 * (1.f / 512.f);
    float q0 = 0.f, q1 = 0.f;
    #pragma unroll
    for (int i = 0; i < 4; i++) {
        float a0 = v0[i].x - mu0, b0 = v0[i].y - mu0, c0 = v0[i].z - mu0, d0 = v0[i].w - mu0;
        float a1 = v1[i].x - mu1, b1 = v1[i].y - mu1, c1 = v1[i].z - mu1, d1 = v1[i].w - mu1;
        q0 += a0 * a0 + b0 * b0 + c0 * c0 + d0 * d0;
        q1 += a1 * a1 + b1 * b1 + c1 * c1 + d1 * d1;
    }
    #pragma unroll
    for (int o = 16; o; o >>= 1) {
        q0 += __shfl_xor_sync(0xffffffffu, q0, o);
        q1 += __shfl_xor_sync(0xffffffffu, q1, o);
    }
    float inv0 = rsqrtf(q0 * (1.f / 512.f) + 1e-5f);
    float inv1 = rsqrtf(q1 * (1.f / 512.f) + 1e-5f);
    bf162* o0p = (bf162*)(out + (long long)row0 * 512);
    bf162* o1p = (bf162*)(out + (long long)(row0 + 1) * 512);
    #pragma unroll
    for (int i = 0; i < 4; i++) {
        float4 gg = ((const float4*)g)[lane + 32 * i];
        float4 bb = ((const float4*)b)[lane + 32 * i];
        o0p[2 * (lane + 32 * i)] =
            __floats2bfloat162_rn((v0[i].x - mu0) * inv0 * gg.x + bb.x,
                                  (v0[i].y - mu0) * inv0 * gg.y + bb.y);
        o0p[2 * (lane + 32 * i) + 1] =
            __floats2bfloat162_rn((v0[i].z - mu0) * inv0 * gg.z + bb.z,
                                  (v0[i].w - mu0) * inv0 * gg.w + bb.w);
        o1p[2 * (lane + 32 * i)] =
            __floats2bfloat162_rn((v1[i].x - mu1) * inv1 * gg.x + bb.x,
                                  (v1[i].y - mu1) * inv1 * gg.y + bb.y);
        o1p[2 * (lane + 32 * i) + 1] =
            __floats2bfloat162_rn((v1[i].z - mu1) * inv1 * gg.z + bb.z,
                                  (v1[i].w - mu1) * inv1 * gg.w + bb.w);
    }
}

// ---------------- window pooling ----------------
__global__ __launch_bounds__(128) void pool_k(const bf16* __restrict__ xn,
                                              const float* __restrict__ wpool,
                                              const float* __restrict__ bpool,
                                              bf16* __restrict__ pooled) {
    int widx = blockIdx.x;
    int ww = widx & 3, wh = (widx >> 2) & 3, bt = widx >> 4;
    int tid = threadIdx.x;
    float a0 = 0.f, a1 = 0.f, a2 = 0.f, a3 = 0.f;
    #pragma unroll
    for (int a = 0; a < 45; a++) {
        int ih = a / 9, iw = a % 9;
        long long tok = ((long long)bt * 20 + wh * 5 + ih) * 36 + ww * 9 + iw;
        uint2 u = *(const uint2*)(xn + tok * 512 + tid * 4);
        float2 f0 = __bfloat1622float2(*(bf162*)&u.x);
        float2 f1 = __bfloat1622float2(*(bf162*)&u.y);
        float w = wpool[a];
        a0 += f0.x * w; a1 += f0.y * w; a2 += f1.x * w; a3 += f1.y * w;
    }
    float bp = bpool[0];
    bf162* dst = (bf162*)(pooled + (long long)widx * 512 + tid * 4);
    dst[0] = __floats2bfloat162_rn(a0 + bp, a1 + bp);
    dst[1] = __floats2bfloat162_rn(a2 + bp, a3 + bp);
}

// ---------------- common PTX helpers ----------------
__device__ __forceinline__ void cpasync16(uint32_t saddr, const void* gaddr, bool pred) {
    int sz = pred ? 16 : 0;
    asm volatile("cp.async.cg.shared.global [%0], [%1], 16, %2;\n"
                 :: "r"(saddr), "l"(gaddr), "r"(sz));
}
__device__ __forceinline__ void ldsm4(uint32_t& r0, uint32_t& r1, uint32_t& r2, uint32_t& r3,
                                      uint32_t a) {
    asm volatile("ldmatrix.sync.aligned.m8n8.x4.shared.b16 {%0,%1,%2,%3}, [%4];\n"
                 : "=r"(r0), "=r"(r1), "=r"(r2), "=r"(r3) : "r"(a));
}
__device__ __forceinline__ void ldsm4t(uint32_t& r0, uint32_t& r1, uint32_t& r2, uint32_t& r3,
                                       uint32_t a) {
    asm volatile("ldmatrix.sync.aligned.m8n8.x4.trans.shared.b16 {%0,%1,%2,%3}, [%4];\n"
                 : "=r"(r0), "=r"(r1), "=r"(r2), "=r"(r3) : "r"(a));
}
__device__ __forceinline__ void mma16816(float* c, const uint32_t* a, const uint32_t* b) {
    asm volatile(
        "mma.sync.aligned.m16n8k16.row.col.f32.bf16.bf16.f32 "
        "{%0,%1,%2,%3}, {%4,%5,%6,%7}, {%8,%9}, {%0,%1,%2,%3};\n"
        : "+f"(c[0]), "+f"(c[1]), "+f"(c[2]), "+f"(c[3])
        : "r"(a[0]), "r"(a[1]), "r"(a[2]), "r"(a[3]), "r"(b[0]), "r"(b[1]));
}
__device__ __forceinline__ uint32_t packbf(float x, float y) {
    bf162 h = __floats2bfloat162_rn(x, y);
    return *(uint32_t*)&h;
}
__device__ __forceinline__ float ex2f(float x) {
    float r;
    asm("ex2.approx.f32 %0, %1;" : "=f"(r) : "f"(x));
    return r;
}
__device__ __forceinline__ void store2(float* p, float x, float y) {
    *(float2*)p = make_float2(x, y);
}
__device__ __forceinline__ void store2(bf16* p, float x, float y) {
    *(bf162*)p = __floats2bfloat162_rn(x, y);
}

// ---------------- fused flash attention: 128 threads, MT=64, KT=64 ----------------
constexpr int FA_KT = 64;
constexpr int FA_ST = 136;

__global__ __launch_bounds__(128) void fattn_k(const bf16* __restrict__ qkv,
                                               const int* __restrict__ qidx,
                                               const int* __restrict__ kidx,
                                               bf16* __restrict__ Og) {
    int mtile = blockIdx.x;                 // 6 tiles of 64 queries
    int zy = blockIdx.y;
    int win = zy >> 2, head = zy & 3;
    int wl = win & 15;
    int mwh = wl >> 2;
    int nk = 1320 + (((mwh == 0) || (mwh == 3)) ? 12 : 16) * 8;

    extern __shared__ bf16 sm[];
    bf16* Ks = sm;                          // [2][64*FA_ST]
    bf16* Vs = sm + 2 * FA_KT * FA_ST;      // [2][64*FA_ST]
    uint32_t sK = (uint32_t)__cvta_generic_to_shared(Ks);
    uint32_t sV = (uint32_t)__cvta_generic_to_shared(Vs);

    int tid = threadIdx.x, wp = tid >> 5, lane = tid & 31;
    int g = lane >> 2, t = lane & 3;
    int hoff = head * 128;

    // ---- load Q tile (64 x 128) into Ks stage 0 ----
    #pragma unroll
    for (int i = 0; i < 8; i++) {
        int idx = tid + i * 128;
        int r = idx >> 4, c = (idx & 15) << 3;
        int q = mtile * 64 + r;
        bool ok = q < 360;
        int e = ok ? __ldg(qidx + win * 360 + q) : 0;
        cpasync16(sK + (uint32_t)((r * FA_ST + c) * 2),
                  qkv + (long long)e * 1536 + hoff + c, ok);
    }
    asm volatile("cp.async.commit_group;\n");
    asm volatile("cp.async.wait_group 0;\n");
    __syncthreads();
    uint32_t qa[8][4];
    #pragma unroll
    for (int ks = 0; ks < 8; ks++) {
        uint32_t ad = sK + (uint32_t)((((wp << 4) + (lane & 15)) * FA_ST
                                       + ks * 16 + ((lane >> 4) << 3)) * 2);
        ldsm4(qa[ks][0], qa[ks][1], qa[ks][2], qa[ks][3], ad);
    }
    __syncthreads();

    auto loadKV = [&](int stage, int kt) {
        #pragma unroll
        for (int i = 0; i < 8; i++) {
            int idx = tid + i * 128;
            int r = idx >> 4, c = (idx & 15) << 3;
            int e = __ldg(kidx + win * NKP + kt * FA_KT + r);
            bool ok = e >= 0;
            const bf16* p = qkv + (long long)(ok ? e : 0) * 1536;
            uint32_t off = (uint32_t)((stage * FA_KT * FA_ST + r * FA_ST + c) * 2);
            cpasync16(sK + off, p + 512 + hoff + c, ok);
            cpasync16(sV + off, p + 1024 + hoff + c, ok);
        }
    };

    float m0 = -1e30f, m1 = -1e30f, l0 = 0.f, l1 = 0.f;
    float o[16][4];
    #pragma unroll
    for (int i = 0; i < 16; i++)
        #pragma unroll
        for (int q = 0; q < 4; q++) o[i][q] = 0.f;

    loadKV(0, 0);
    asm volatile("cp.async.commit_group;\n");

    for (int kt = 0; kt < NKT; kt++) {
        if (kt + 1 < NKT) loadKV((kt + 1) & 1, kt + 1);
        asm volatile("cp.async.commit_group;\n");
        asm volatile("cp.async.wait_group %0;\n" :: "n"(1));
        __syncthreads();

        uint32_t bK = sK + (uint32_t)((kt & 1) * FA_KT * FA_ST * 2);
        uint32_t bV = sV + (uint32_t)((kt & 1) * FA_KT * FA_ST * 2);

        float c[8][4];
        #pragma unroll
        for (int n = 0; n < 8; n++)
            #pragma unroll
            for (int q = 0; q < 4; q++) c[n][q] = 0.f;

        #pragma unroll
        for (int ks = 0; ks < 8; ks++) {
            #pragma unroll
            for (int h = 0; h < 4; h++) {
                uint32_t b[4];
                uint32_t bd = bK + (uint32_t)(((h * 16 + (lane & 7) + ((lane >> 4) << 3)) * FA_ST
                                              + ks * 16 + (((lane >> 3) & 1) << 3)) * 2);
                ldsm4(b[0], b[1], b[2], b[3], bd);
                mma16816(c[2 * h], qa[ks], b);
                mma16816(c[2 * h + 1], qa[ks], b + 2);
            }
        }

        #pragma unroll
        for (int n = 0; n < 8; n++)
            #pragma unroll
            for (int q = 0; q < 4; q++) c[n][q] *= SC2;

        if (kt == NKT - 1) {
            #pragma unroll
            for (int n = 0; n < 8; n++) {
                #pragma unroll
                for (int e = 0; e < 2; e++) {
                    int j = (NKT - 1) * FA_KT + n * 8 + 2 * t + e;
                    if (j >= nk) { c[n][e] = -1e30f; c[n][e + 2] = -1e30f; }
                }
            }
        }

        float r0 = -1e30f, r1 = -1e30f;
        #pragma unroll
        for (int n = 0; n < 8; n++) {
            r0 = fmaxf(r0, fmaxf(c[n][0], c[n][1]));
            r1 = fmaxf(r1, fmaxf(c[n][2], c[n][3]));
        }
        r0 = fmaxf(r0, __shfl_xor_sync(0xffffffffu, r0, 1));
        r0 = fmaxf(r0, __shfl_xor_sync(0xffffffffu, r0, 2));
        r1 = fmaxf(r1, __shfl_xor_sync(0xffffffffu, r1, 1));
        r1 = fmaxf(r1, __shfl_xor_sync(0xffffffffu, r1, 2));
        float mn0 = fmaxf(m0, r0), mn1 = fmaxf(m1, r1);
        float sc0 = ex2f(m0 - mn0), sc1 = ex2f(m1 - mn1);
        m0 = mn0; m1 = mn1;
        float s0 = 0.f, s1 = 0.f;
        #pragma unroll
        for (int n = 0; n < 8; n++) {
            c[n][0] = ex2f(c[n][0] - mn0);
            c[n][1] = ex2f(c[n][1] - mn0);
            c[n][2] = ex2f(c[n][2] - mn1);
            c[n][3] = ex2f(c[n][3] - mn1);
            s0 += c[n][0] + c[n][1];
            s1 += c[n][2] + c[n][3];
        }
        s0 += __shfl_xor_sync(0xffffffffu, s0, 1);
        s0 += __shfl_xor_sync(0xffffffffu, s0, 2);
        s1 += __shfl_xor_sync(0xffffffffu, s1, 1);
        s1 += __shfl_xor_sync(0xffffffffu, s1, 2);
        l0 = l0 * sc0 + s0;
        l1 = l1 * sc1 + s1;
        #pragma unroll
        for (int i = 0; i < 16; i++) {
            o[i][0] *= sc0; o[i][1] *= sc0;
            o[i][2] *= sc1; o[i][3] *= sc1;
        }

        #pragma unroll
        for (int kk = 0; kk < 4; kk++) {
            uint32_t a[4];
            a[0] = packbf(c[2 * kk][0], c[2 * kk][1]);
            a[1] = packbf(c[2 * kk][2], c[2 * kk][3]);
            a[2] = packbf(c[2 * kk + 1][0], c[2 * kk + 1][1]);
            a[3] = packbf(c[2 * kk + 1][2], c[2 * kk + 1][3]);
            #pragma unroll
            for (int h = 0; h < 8; h++) {
                uint32_t b[4];
                uint32_t bd = bV + (uint32_t)(((kk * 16 + (lane & 7) + (((lane >> 3) & 1) << 3)) * FA_ST
                                              + h * 16 + ((lane >> 4) << 3)) * 2);
                ldsm4t(b[0], b[1], b[2], b[3], bd);
                mma16816(o[2 * h], a, b);
                mma16816(o[2 * h + 1], a, b + 2);
            }
        }
        __syncthreads();
    }

    float il0 = 1.f / l0, il1 = 1.f / l1;
    int q0 = mtile * 64 + wp * 16 + g;
    #pragma unroll
    for (int h = 0; h < 16; h++) {
        int col = hoff + h * 8 + 2 * t;
        if (q0 < 360) {
            bf162 v = __floats2bfloat162_rn(o[h][0] * il0, o[h][1] * il0);
            *(bf162*)(Og + ((long long)win * 360 + q0) * 512 + col) = v;
        }
        if (q0 + 8 < 360) {
            bf162 v = __floats2bfloat162_rn(o[h][2] * il1, o[h][3] * il1);
            *(bf162*)(Og + ((long long)win * 360 + q0 + 8) * 512 + col) = v;
        }
    }
}

// ---------------- bf16 GEMM: BM template (128/64), BN=128, BK=64, 3-stage ----------
constexpr int GBN = 128, GBK = 64;
constexpr int GAST = GBK + 8;    // 72
constexpr int GBST = GBN + 8;    // 136
constexpr int GBSZ = GBK * GBST; // 8704

template <typename OutT, int BMT>
__global__ __launch_bounds__(256, 2) void tgemm_k(
    const bf16* __restrict__ A, const bf16* __restrict__ Bm,
    const float* __restrict__ bias, const float* __restrict__ res,
    OutT* __restrict__ Cm, int M, int N, int K,
    const int* __restrict__ scat) {
    constexpr int GASZ = BMT * GAST;
    constexpr int MI = BMT / 64;
    constexpr int ALOAD = BMT / 32;
    extern __shared__ bf16 smem[];
    bf16* As = smem;
    bf16* Bs = smem + 3 * GASZ;

    int tid = threadIdx.x;
    int row0 = blockIdx.y * BMT, col0 = blockIdx.x * GBN;
    int wid = tid >> 5, lane = tid & 31;
    int wm = wid & 3, wn = wid >> 2;
    int g = lane >> 2, t = lane & 3;

    uint32_t sA0 = (uint32_t)__cvta_generic_to_shared(As);
    uint32_t sB0 = (uint32_t)__cvta_generic_to_shared(Bs);
    int ktiles = (K + GBK - 1) / GBK;

    auto load_tile = [&](int stage, int k0) {
        #pragma unroll
        for (int i = 0; i < ALOAD; i++) {
            int idx = tid + i * 256;
            int r = idx >> 3, kc = (idx & 7) << 3;
            bool ok = (k0 + kc) < K;
            cpasync16(sA0 + (uint32_t)((stage * GASZ + r * GAST + kc) * 2),
                      A + (long long)(row0 + r) * K + k0 + kc, ok);
        }
        #pragma unroll
        for (int i = 0; i < 4; i++) {
            int idx = tid + i * 256;
            int kk = idx >> 4, nc = (idx & 15) << 3;
            int gn = col0 + nc;
            bool ok = ((k0 + kk) < K) && (gn < N);
            cpasync16(sB0 + (uint32_t)((stage * GBSZ + kk * GBST + nc) * 2),
                      Bm + (long long)(k0 + kk) * N + gn, ok);
        }
    };

    float acc[MI][8][4];
    #pragma unroll
    for (int mi = 0; mi < MI; mi++)
        #pragma unroll
        for (int ni = 0; ni < 8; ni++)
            #pragma unroll
            for (int q = 0; q < 4; q++) acc[mi][ni][q] = 0.f;

    load_tile(0, 0);
    asm volatile("cp.async.commit_group;\n");
    load_tile(1, GBK);
    asm volatile("cp.async.commit_group;\n");

    for (int kt = 0; kt < ktiles; kt++) {
        asm volatile("cp.async.wait_group %0;\n" :: "n"(1));
        __syncthreads();
        if (kt + 2 < ktiles) load_tile((kt + 2) % 3, (kt + 2) * GBK);
        asm volatile("cp.async.commit_group;\n");

        uint32_t sAb = sA0 + (uint32_t)((kt % 3) * GASZ * 2);
        uint32_t sBb = sB0 + (uint32_t)((kt % 3) * GBSZ * 2);

        #pragma unroll
        for (int ks = 0; ks < 4; ks++) {
            uint32_t a[MI][4], b[8][2];
            #pragma unroll
            for (int mi = 0; mi < MI; mi++) {
                int row = wm * (BMT / 4) + mi * 16 + (lane & 15);
                uint32_t ad = sAb + (uint32_t)((row * GAST + ks * 16 + ((lane >> 4) << 3)) * 2);
                ldsm4(a[mi][0], a[mi][1], a[mi][2], a[mi][3], ad);
            }
            #pragma unroll
            for (int h = 0; h < 4; h++) {
                int rowk = ks * 16 + (lane & 7) + (((lane >> 3) & 1) << 3);
                int coln = wn * 64 + h * 16 + ((lane >> 4) << 3);
                uint32_t bd = sBb + (uint32_t)((rowk * GBST + coln) * 2);
                ldsm4t(b[2 * h][0], b[2 * h][1], b[2 * h + 1][0], b[2 * h + 1][1], bd);
            }
            #pragma unroll
            for (int mi = 0; mi < MI; mi++)
                #pragma unroll
                for (int ni = 0; ni < 8; ni++)
                    mma16816(acc[mi][ni], a[mi], b[ni]);
        }
    }

    #pragma unroll
    for (int mi = 0; mi < MI; mi++) {
        int r = row0 + wm * (BMT / 4) + mi * 16 + g;
        int ra = scat ? __ldg(scat + r) : r;
        int rb = scat ? __ldg(scat + r + 8) : r + 8;
        #pragma unroll
        for (int ni = 0; ni < 8; ni++) {
            int cidx = col0 + wn * 64 + ni * 8 + 2 * t;
            if (cidx < N) {
                float b0 = bias ? bias[cidx] : 0.f;
                float b1 = bias ? bias[cidx + 1] : 0.f;
                float x0 = acc[mi][ni][0] + b0, x1 = acc[mi][ni][1] + b1;
                float x2 = acc[mi][ni][2] + b0, x3 = acc[mi][ni][3] + b1;
                long long i0 = (long long)ra * N + cidx;
                long long i1 = (long long)rb * N + cidx;
                if (res) {
                    float2 r0 = *(const float2*)(res + i0);
                    float2 r1 = *(const float2*)(res + i1);
                    x0 += r0.x; x1 += r0.y; x2 += r1.x; x3 += r1.y;
                }
                store2(Cm + i0, x0, x1);
                store2(Cm + i1, x2, x3);
            }
        }
    }
}

// ---------------- T2T fold (gather form, bf16 in) + normalize ----------------
__global__ __launch_bounds__(256) void t2tfold_k(const bf16* __restrict__ h1,
                                                 float* __restrict__ I) {
    int idx = blockIdx.x * 256 + threadIdx.x;
    if (idx >= 16 * 40 * 60 * 108) return;
    int x = idx % 108;
    int y = (idx / 108) % 60;
    int c40 = (idx / (108 * 60)) % 40;
    int g = idx / (108 * 60 * 40);
    int pys[3], kis[3], pxs[3], kjs[3];
    int cy = 0, cx = 0;
    #pragma unroll
    for (int dp = 0; dp < 3; dp++) {
        int py = (y + 3) / 3 - dp;
        int ki = y + 3 - 3 * py;
        if (py >= 0 && py < 20 && ki < 7) { pys[cy] = py; kis[cy] = ki; cy++; }
        int px = (x + 3) / 3 - dp;
        int kj = x + 3 - 3 * px;
        if (px >= 0 && px < 36 && kj < 7) { pxs[cx] = px; kjs[cx] = kj; cx++; }
    }
    float s = 0.f;
    for (int a = 0; a < cy; a++)
        for (int bb = 0; bb < cx; bb++) {
            long long r = (long long)g * 720 + pys[a] * 36 + pxs[bb];
            s += __bfloat162float(h1[r * 1960 + c40 * 49 + kis[a] * 7 + kjs[bb]]);
        }
    I[idx] = s / (float)(cy * cx);
}

// ---------------- T2T unfold + exact GELU (paired bf162 out) ----------------
__global__ __launch_bounds__(256) void t2tunf_k(const float* __restrict__ I,
                                                bf16* __restrict__ h2) {
    int idx2 = blockIdx.x * 256 + threadIdx.x;
    if (idx2 >= TOK * FFN / 2) return;
    float vv[2];
    #pragma unroll
    for (int e = 0; e < 2; e++) {
        int idx = 2 * idx2 + e;
        int c = idx % 1960;
        int r = idx / 1960;
        int g = r / 720;
        int p = r - g * 720;
        int py = p / 36, px = p - py * 36;
        int c40 = c / 49;
        int kk = c - c40 * 49;
        int ki = kk / 7, kj = kk - ki * 7;
        int y = py * 3 + ki - 3, x = px * 3 + kj - 3;
        float v = 0.f;
        if (y >= 0 && y < 60 && x >= 0 && x < 108)
            v = I[(((long long)g * 40 + c40) * 60 + y) * 108 + x];
        vv[e] = 0.5f * v * (1.f + erff(v * 0.7071067811865475f));
    }
    ((bf162*)h2)[idx2] = __floats2bfloat162_rn(vv[0], vv[1]);
}

// ---------------- host launch ----------------
#define SYM(T, p, s) T* p; do { void* _t = nullptr; cudaGetSymbolAddress(&_t, s); (p) = (T*)_t; } while (0)

template <typename OutT, int BMT>
static void run_tgemm(const bf16* A, const bf16* Bm, const float* bias,
                      const float* res, OutT* C, int M, int N, int K,
                      const int* scat = nullptr) {
    dim3 grid((N + GBN - 1) / GBN, M / BMT);
    size_t sm = (size_t)3 * (BMT * GAST + GBSZ) * sizeof(bf16);
    cudaFuncSetAttribute(tgemm_k<OutT, BMT>, cudaFuncAttributeMaxDynamicSharedMemorySize, (int)sm);
    tgemm_k<OutT, BMT><<<grid, 256, sm>>>(A, Bm, bias, res, C, M, N, K, scat);
}

extern "C" void kernel_launch(void* const* d_in, const int* in_sizes, int n_in,
                              void* d_out, int out_size) {
    const float* x     = (const float*)d_in[0];
    const float* g1    = (const float*)d_in[1];
    const float* be1   = (const float*)d_in[2];
    const float* wqkv  = (const float*)d_in[3];
    const float* bqkv  = (const float*)d_in[4];
    const float* wproj = (const float*)d_in[5];
    const float* bproj = (const float*)d_in[6];
    const float* wpool = (const float*)d_in[7];
    const float* bpool = (const float*)d_in[8];
    const float* g2    = (const float*)d_in[9];
    const float* be2   = (const float*)d_in[10];
    const float* w1    = (const float*)d_in[11];
    const float* bf1   = (const float*)d_in[12];
    const float* w2    = (const float*)d_in[13];
    const float* bf2   = (const float*)d_in[14];
    float* out = (float*)d_out;

    SYM(bf16, xn, g_xn); SYM(bf16, qkv, g_qkv); SYM(bf16, Aw, g_Aw);
    SYM(float, xres, g_xres); SYM(bf16, hb, g_hb); SYM(float, I, g_I);
    SYM(int, qidx, g_qidx); SYM(int, kidx, g_kidx);
    SYM(bf16, wb, g_wb);
    bf16* wqkvb  = wb;
    bf16* wprojb = wb + WO_PROJ;
    bf16* w1b    = wb + WO_W1;
    bf16* w2b    = wb + WO_W2;

    initvalid_k<<<1, 32>>>();
    idx_k<<<(NWIN * NKP + 255) / 256, 256>>>(qidx, kidx);
    convw_all<<<(WTOT / 4 + 255) / 256, 256>>>(wqkv, wproj, w1, w2, wb);

    ln_k<<<TOK / 16, 256>>>(x, g1, be1, xn);
    pool_k<<<256, 128>>>(xn, wpool, bpool, xn + (long long)TOK * 512);
    run_tgemm<bf16, 128>(xn, wqkvb, bqkv, nullptr, qkv, MTOT, 1536, 512);

    {
        size_t smfa = (size_t)4 * FA_KT * FA_ST * sizeof(bf16);  // 69632 B
        cudaFuncSetAttribute(fattn_k, cudaFuncAttributeMaxDynamicSharedMemorySize, (int)smfa);
        fattn_k<<<dim3(6, 128), 128, smfa>>>(qkv, qidx, kidx, Aw);
    }

    run_tgemm<float, 64>(Aw, wprojb, bproj, x, xres, TOK, 512, 512, qidx);
    ln_k<<<TOK / 16, 256>>>(xres, g2, be2, xn);
    run_tgemm<bf16, 128>(xn, w1b, bf1, nullptr, hb, TOK, FFN, 512);
    t2tfold_k<<<(16 * 40 * 60 * 108 + 255) / 256, 256>>>(hb, I);
    t2tunf_k<<<(TOK * FFN / 2 + 255) / 256, 256>>>(I, hb);
    run_tgemm<float, 64>(hb, w2b, bf2, xres, out, TOK, 512, FFN);
}

// round 12
// speedup vs baseline: 1.0450x; 1.0450x over previous
#include <cuda_runtime.h>
#include <cuda_bf16.h>
#include <math.h>
#include <stdint.h>

// ---------------- constants ----------------
constexpr int NWIN = 32;
constexpr int NQ = 360;
constexpr int NKP = 1456;          // compacted+padded keys = 13 * 112
constexpr int NKT = 13;            // key tiles
constexpr int TOK = 11520;
constexpr int MTOT = TOK + 256;    // tokens + pooled rows (11776 = 92*128)
constexpr int FFN = 1960;
constexpr int Cch = 512;
constexpr float SC2 = 0.08838834764831845f * 1.4426950408889634f; // qscale * log2(e)

typedef __nv_bfloat16 bf16;
typedef __nv_bfloat162 bf162;

// ---------------- scratch ----------------
__device__ bf16  g_xn[MTOT * Cch];
__device__ bf16  g_qkv[MTOT * 3 * Cch];
__device__ bf16  g_Aw[TOK * Cch];
__device__ float g_xres[TOK * Cch];
__device__ bf16  g_hb[TOK * FFN];
__device__ float g_I[16 * 40 * 60 * 108];
__device__ int   g_valid[120];
__device__ int   g_qidx[NWIN * NQ];
__device__ int   g_kidx[NWIN * NKP];
__device__ bf16  g_wb[3055616];
constexpr int WO_PROJ = 786432;
constexpr int WO_W1   = 1048576;
constexpr int WO_W2   = 2052096;
constexpr int WTOT    = 3055616;

// ---------------- init valid-rolled table ----------------
__global__ void initvalid_k() {
    if (threadIdx.x == 0 && blockIdx.x == 0) {
        int n = 0;
        for (int s = 0; s < 4; s++)
            for (int ih = 0; ih < 5; ih++)
                for (int iw = 0; iw < 9; iw++) {
                    bool zero;
                    if (s == 0) zero = (ih < 3 && iw < 5);
                    else if (s == 1) zero = (ih < 3 && iw >= 4);
                    else if (s == 2) zero = (ih >= 2 && iw < 5);
                    else zero = (ih >= 2 && iw >= 4);
                    if (!zero) g_valid[n++] = s * 45 + ih * 9 + iw;
                }
    }
}

// ---------------- build gather index tables ----------------
__global__ __launch_bounds__(256) void idx_k(int* __restrict__ qidx,
                                             int* __restrict__ kidx) {
    int i = blockIdx.x * 256 + threadIdx.x;
    if (i < NWIN * NQ) {
        int win = i / NQ, q = i - win * NQ;
        int b = win >> 4, wh = (win >> 2) & 3, ww = win & 3;
        int t = q / 45, a = q - t * 45, ih = a / 9, iw = a % 9;
        qidx[i] = ((b * 8 + t) * 20 + wh * 5 + ih) * 36 + ww * 9 + iw;
    }
    if (i < NWIN * NKP) {
        int win = i / NKP, j = i - win * NKP;
        int b = win >> 4, wh = (win >> 2) & 3, ww = win & 3;
        int e = -1;
        if (j < 360) {
            int t = j / 45, a = j - t * 45, ih = a / 9, iw = a % 9;
            e = ((b * 8 + t) * 20 + wh * 5 + ih) * 36 + ww * 9 + iw;
        } else if (j < 1320) {
            int jj = j - 360;
            int t = jj / 120, vi = jj - t * 120;
            int f = g_valid[vi];
            int s = f / 45, a = f - s * 45, ih = a / 9, iw = a % 9;
            int sh = (s < 2) ? -2 : 2;
            int sw = (s & 1) ? 4 : -4;
            int hh = wh * 5 + ih - sh; hh %= 20; if (hh < 0) hh += 20;
            int wp = ww * 9 + iw - sw; wp %= 36; if (wp < 0) wp += 36;
            e = ((b * 8 + t) * 20 + hh) * 36 + wp;
        } else {
            int pos = j - 1320;
            int i0 = (2 - wh) > 0 ? (2 - wh) : 0;
            int iend = (6 - wh) < 5 ? (6 - wh) : 5;
            int rows = iend - i0;
            int nv = rows * 4;
            if (pos < nv * 8) {
                int t = pos / nv, r = pos - t * nv;
                int di = r >> 2, dj = r & 3;
                int gi = wh + (i0 + di) - 2;
                int gj = dj;
                e = TOK + (b * 8 + t) * 16 + gi * 4 + gj;
            }
        }
        kidx[i] = e;
    }
}

// ---------------- all weights fp32 -> bf16 ----------------
__global__ __launch_bounds__(256) void convw_all(const float* __restrict__ a,
                                                 const float* __restrict__ b,
                                                 const float* __restrict__ c,
                                                 const float* __restrict__ d,
                                                 bf16* __restrict__ o) {
    int i4 = (blockIdx.x * 256 + threadIdx.x) * 4;
    if (i4 >= WTOT) return;
    const float* src;
    int off;
    if (i4 < WO_PROJ)      { src = a; off = i4; }
    else if (i4 < WO_W1)   { src = b; off = i4 - WO_PROJ; }
    else if (i4 < WO_W2)   { src = c; off = i4 - WO_W1; }
    else                   { src = d; off = i4 - WO_W2; }
    float4 v = *(const float4*)(src + off);
    *(bf162*)(o + i4)     = __floats2bfloat162_rn(v.x, v.y);
    *(bf162*)(o + i4 + 2) = __floats2bfloat162_rn(v.z, v.w);
}

// ---------------- LayerNorm: warp per row, 8 rows/block ----------------
__global__ __launch_bounds__(256) void ln_k(const float* __restrict__ in,
                                            const float* __restrict__ g,
                                            const float* __restrict__ b,
                                            bf16* __restrict__ out) {
    int row = blockIdx.x * 8 + (threadIdx.x >> 5);
    int lane = threadIdx.x & 31;
    const float4* xp = (const float4*)(in + (long long)row * 512);
    float4 v[4];
    float s = 0.f;
    #pragma unroll
    for (int i = 0; i < 4; i++) {
        v[i] = xp[lane + 32 * i];
        s += v[i].x + v[i].y + v[i].z + v[i].w;
    }
    #pragma unroll
    for (int o = 16; o; o >>= 1) s += __shfl_xor_sync(0xffffffffu, s, o);
    float mu = s * (1.f / 512.f);
    float sq = 0.f;
    #pragma unroll
    for (int i = 0; i < 4; i++) {
        float dx = v[i].x - mu, dy = v[i].y - mu, dz = v[i].z - mu, dw = v[i].w - mu;
        sq += dx * dx + dy * dy + dz * dz + dw * dw;
    }
    #pragma unroll
    for (int o = 16; o; o >>= 1) sq += __shfl_xor_sync(0xffffffffu, sq, o);
    float inv = rsqrtf(sq * (1.f / 512.f) + 1e-5f);
    bf162* op = (bf162*)(out + (long long)row * 512);
    #pragma unroll
    for (int i = 0; i < 4; i++) {
        float4 gg = ((const float4*)g)[lane + 32 * i];
        float4 bb = ((const float4*)b)[lane + 32 * i];
        bf162 o0 = __floats2bfloat162_rn((v[i].x - mu) * inv * gg.x + bb.x,
                                         (v[i].y - mu) * inv * gg.y + bb.y);
        bf162 o1 = __floats2bfloat162_rn((v[i].z - mu) * inv * gg.z + bb.z,
                                         (v[i].w - mu) * inv * gg.w + bb.w);
        op[2 * (lane + 32 * i)] = o0;
        op[2 * (lane + 32 * i) + 1] = o1;
    }
}

// ---------------- window pooling ----------------
__global__ __launch_bounds__(128) void pool_k(const bf16* __restrict__ xn,
                                              const float* __restrict__ wpool,
                                              const float* __restrict__ bpool,
                                              bf16* __restrict__ pooled) {
    int widx = blockIdx.x;
    int ww = widx & 3, wh = (widx >> 2) & 3, bt = widx >> 4;
    int tid = threadIdx.x;
    float a0 = 0.f, a1 = 0.f, a2 = 0.f, a3 = 0.f;
    #pragma unroll
    for (int a = 0; a < 45; a++) {
        int ih = a / 9, iw = a % 9;
        long long tok = ((long long)bt * 20 + wh * 5 + ih) * 36 + ww * 9 + iw;
        uint2 u = *(const uint2*)(xn + tok * 512 + tid * 4);
        float2 f0 = __bfloat1622float2(*(bf162*)&u.x);
        float2 f1 = __bfloat1622float2(*(bf162*)&u.y);
        float w = wpool[a];
        a0 += f0.x * w; a1 += f0.y * w; a2 += f1.x * w; a3 += f1.y * w;
    }
    float bp = bpool[0];
    bf162* dst = (bf162*)(pooled + (long long)widx * 512 + tid * 4);
    dst[0] = __floats2bfloat162_rn(a0 + bp, a1 + bp);
    dst[1] = __floats2bfloat162_rn(a2 + bp, a3 + bp);
}

// ---------------- common PTX helpers ----------------
__device__ __forceinline__ void cpasync16(uint32_t saddr, const void* gaddr, bool pred) {
    int sz = pred ? 16 : 0;
    asm volatile("cp.async.cg.shared.global [%0], [%1], 16, %2;\n"
                 :: "r"(saddr), "l"(gaddr), "r"(sz));
}
__device__ __forceinline__ void ldsm4(uint32_t& r0, uint32_t& r1, uint32_t& r2, uint32_t& r3,
                                      uint32_t a) {
    asm volatile("ldmatrix.sync.aligned.m8n8.x4.shared.b16 {%0,%1,%2,%3}, [%4];\n"
                 : "=r"(r0), "=r"(r1), "=r"(r2), "=r"(r3) : "r"(a));
}
__device__ __forceinline__ void ldsm4t(uint32_t& r0, uint32_t& r1, uint32_t& r2, uint32_t& r3,
                                       uint32_t a) {
    asm volatile("ldmatrix.sync.aligned.m8n8.x4.trans.shared.b16 {%0,%1,%2,%3}, [%4];\n"
                 : "=r"(r0), "=r"(r1), "=r"(r2), "=r"(r3) : "r"(a));
}
__device__ __forceinline__ void mma16816(float* c, const uint32_t* a, const uint32_t* b) {
    asm volatile(
        "mma.sync.aligned.m16n8k16.row.col.f32.bf16.bf16.f32 "
        "{%0,%1,%2,%3}, {%4,%5,%6,%7}, {%8,%9}, {%0,%1,%2,%3};\n"
        : "+f"(c[0]), "+f"(c[1]), "+f"(c[2]), "+f"(c[3])
        : "r"(a[0]), "r"(a[1]), "r"(a[2]), "r"(a[3]), "r"(b[0]), "r"(b[1]));
}
__device__ __forceinline__ uint32_t packbf(float x, float y) {
    bf162 h = __floats2bfloat162_rn(x, y);
    return *(uint32_t*)&h;
}
__device__ __forceinline__ float ex2f(float x) {
    float r;
    asm("ex2.approx.f32 %0, %1;" : "=f"(r) : "f"(x));
    return r;
}
__device__ __forceinline__ void store2(float* p, float x, float y) {
    *(float2*)p = make_float2(x, y);
}
__device__ __forceinline__ void store2(bf16* p, float x, float y) {
    *(bf162*)p = __floats2bfloat162_rn(x, y);
}

// ---------------- fused flash attention: MT=128, KT=112, 256 threads (R10 config) ------
constexpr int FA_KT = 112;
constexpr int FA_ST = 136;

__global__ __launch_bounds__(256, 1) void fattn_k(const bf16* __restrict__ qkv,
                                                  const int* __restrict__ qidx,
                                                  const int* __restrict__ kidx,
                                                  bf16* __restrict__ Og) {
    int mtile = blockIdx.x;
    int zy = blockIdx.y;
    int win = zy >> 2, head = zy & 3;
    int wl = win & 15;
    int mwh = wl >> 2;
    int nk = 1320 + (((mwh == 0) || (mwh == 3)) ? 12 : 16) * 8;

    extern __shared__ bf16 sm[];
    bf16* Ks = sm;
    bf16* Vs = sm + 2 * FA_KT * FA_ST;
    uint32_t sK = (uint32_t)__cvta_generic_to_shared(Ks);
    uint32_t sV = (uint32_t)__cvta_generic_to_shared(Vs);

    int tid = threadIdx.x, wp = tid >> 5, lane = tid & 31;
    int g = lane >> 2, t = lane & 3;
    int hoff = head * 128;

    // ---- load Q tile ----
    #pragma unroll
    for (int i = 0; i < 8; i++) {
        int idx = tid + i * 256;
        int r = idx >> 4, c = (idx & 15) << 3;
        int q = mtile * 128 + r;
        bool ok = q < 360;
        int e = ok ? __ldg(qidx + win * 360 + q) : 0;
        cpasync16(sK + (uint32_t)((r * FA_ST + c) * 2),
                  qkv + (long long)e * 1536 + hoff + c, ok);
    }
    asm volatile("cp.async.commit_group;\n");
    asm volatile("cp.async.wait_group 0;\n");
    __syncthreads();
    uint32_t qa[8][4];
    #pragma unroll
    for (int ks = 0; ks < 8; ks++) {
        uint32_t ad = sK + (uint32_t)((((wp << 4) + (lane & 15)) * FA_ST
                                       + ks * 16 + ((lane >> 4) << 3)) * 2);
        ldsm4(qa[ks][0], qa[ks][1], qa[ks][2], qa[ks][3], ad);
    }
    __syncthreads();

    auto loadKV = [&](int stage, int kt) {
        #pragma unroll
        for (int i = 0; i < 7; i++) {
            int idx = tid + i * 256;
            int r = idx >> 4, c = (idx & 15) << 3;
            int e = __ldg(kidx + win * NKP + kt * FA_KT + r);
            bool ok = e >= 0;
            const bf16* p = qkv + (long long)(ok ? e : 0) * 1536;
            uint32_t off = (uint32_t)((stage * FA_KT * FA_ST + r * FA_ST + c) * 2);
            cpasync16(sK + off, p + 512 + hoff + c, ok);
            cpasync16(sV + off, p + 1024 + hoff + c, ok);
        }
    };

    float m0 = -1e30f, m1 = -1e30f, l0 = 0.f, l1 = 0.f;
    float o[16][4];
    #pragma unroll
    for (int i = 0; i < 16; i++)
        #pragma unroll
        for (int q = 0; q < 4; q++) o[i][q] = 0.f;

    loadKV(0, 0);
    asm volatile("cp.async.commit_group;\n");

    for (int kt = 0; kt < NKT; kt++) {
        if (kt + 1 < NKT) loadKV((kt + 1) & 1, kt + 1);
        asm volatile("cp.async.commit_group;\n");
        asm volatile("cp.async.wait_group %0;\n" :: "n"(1));
        __syncthreads();

        uint32_t bK = sK + (uint32_t)((kt & 1) * FA_KT * FA_ST * 2);
        uint32_t bV = sV + (uint32_t)((kt & 1) * FA_KT * FA_ST * 2);

        float c[14][4];
        #pragma unroll
        for (int n = 0; n < 14; n++)
            #pragma unroll
            for (int q = 0; q < 4; q++) c[n][q] = 0.f;

        #pragma unroll
        for (int ks = 0; ks < 8; ks++) {
            #pragma unroll
            for (int h = 0; h < 7; h++) {
                uint32_t b[4];
                uint32_t bd = bK + (uint32_t)(((h * 16 + (lane & 7) + ((lane >> 4) << 3)) * FA_ST
                                              + ks * 16 + (((lane >> 3) & 1) << 3)) * 2);
                ldsm4(b[0], b[1], b[2], b[3], bd);
                mma16816(c[2 * h], qa[ks], b);
                mma16816(c[2 * h + 1], qa[ks], b + 2);
            }
        }

        #pragma unroll
        for (int n = 0; n < 14; n++)
            #pragma unroll
            for (int q = 0; q < 4; q++) c[n][q] *= SC2;

        if (kt == NKT - 1) {
            #pragma unroll
            for (int n = 0; n < 14; n++) {
                #pragma unroll
                for (int e = 0; e < 2; e++) {
                    int j = (NKT - 1) * FA_KT + n * 8 + 2 * t + e;
                    if (j >= nk) { c[n][e] = -1e30f; c[n][e + 2] = -1e30f; }
                }
            }
        }

        float r0 = -1e30f, r1 = -1e30f;
        #pragma unroll
        for (int n = 0; n < 14; n++) {
            r0 = fmaxf(r0, fmaxf(c[n][0], c[n][1]));
            r1 = fmaxf(r1, fmaxf(c[n][2], c[n][3]));
        }
        r0 = fmaxf(r0, __shfl_xor_sync(0xffffffffu, r0, 1));
        r0 = fmaxf(r0, __shfl_xor_sync(0xffffffffu, r0, 2));
        r1 = fmaxf(r1, __shfl_xor_sync(0xffffffffu, r1, 1));
        r1 = fmaxf(r1, __shfl_xor_sync(0xffffffffu, r1, 2));
        float mn0 = fmaxf(m0, r0), mn1 = fmaxf(m1, r1);
        float sc0 = ex2f(m0 - mn0), sc1 = ex2f(m1 - mn1);
        m0 = mn0; m1 = mn1;
        float s0 = 0.f, s1 = 0.f;
        #pragma unroll
        for (int n = 0; n < 14; n++) {
            c[n][0] = ex2f(c[n][0] - mn0);
            c[n][1] = ex2f(c[n][1] - mn0);
            c[n][2] = ex2f(c[n][2] - mn1);
            c[n][3] = ex2f(c[n][3] - mn1);
            s0 += c[n][0] + c[n][1];
            s1 += c[n][2] + c[n][3];
        }
        s0 += __shfl_xor_sync(0xffffffffu, s0, 1);
        s0 += __shfl_xor_sync(0xffffffffu, s0, 2);
        s1 += __shfl_xor_sync(0xffffffffu, s1, 1);
        s1 += __shfl_xor_sync(0xffffffffu, s1, 2);
        l0 = l0 * sc0 + s0;
        l1 = l1 * sc1 + s1;
        #pragma unroll
        for (int i = 0; i < 16; i++) {
            o[i][0] *= sc0; o[i][1] *= sc0;
            o[i][2] *= sc1; o[i][3] *= sc1;
        }

        #pragma unroll
        for (int kk = 0; kk < 7; kk++) {
            uint32_t a[4];
            a[0] = packbf(c[2 * kk][0], c[2 * kk][1]);
            a[1] = packbf(c[2 * kk][2], c[2 * kk][3]);
            a[2] = packbf(c[2 * kk + 1][0], c[2 * kk + 1][1]);
            a[3] = packbf(c[2 * kk + 1][2], c[2 * kk + 1][3]);
            #pragma unroll
            for (int h = 0; h < 8; h++) {
                uint32_t b[4];
                uint32_t bd = bV + (uint32_t)(((kk * 16 + (lane & 7) + (((lane >> 3) & 1) << 3)) * FA_ST
                                              + h * 16 + ((lane >> 4) << 3)) * 2);
                ldsm4t(b[0], b[1], b[2], b[3], bd);
                mma16816(o[2 * h], a, b);
                mma16816(o[2 * h + 1], a, b + 2);
            }
        }
        __syncthreads();
    }

    float il0 = 1.f / l0, il1 = 1.f / l1;
    int q0 = mtile * 128 + wp * 16 + g;
    #pragma unroll
    for (int h = 0; h < 16; h++) {
        int col = hoff + h * 8 + 2 * t;
        if (q0 < 360) {
            bf162 v = __floats2bfloat162_rn(o[h][0] * il0, o[h][1] * il0);
            *(bf162*)(Og + ((long long)win * 360 + q0) * 512 + col) = v;
        }
        if (q0 + 8 < 360) {
            bf162 v = __floats2bfloat162_rn(o[h][2] * il1, o[h][3] * il1);
            *(bf162*)(Og + ((long long)win * 360 + q0 + 8) * 512 + col) = v;
        }
    }
}

// ---------------- bf16 GEMM: BM template (128/64), BN=128, BK=64, 3-stage ----------
constexpr int GBN = 128, GBK = 64;
constexpr int GAST = GBK + 8;    // 72
constexpr int GBST = GBN + 8;    // 136
constexpr int GBSZ = GBK * GBST; // 8704

template <typename OutT, int BMT>
__global__ __launch_bounds__(256, 2) void tgemm_k(
    const bf16* __restrict__ A, const bf16* __restrict__ Bm,
    const float* __restrict__ bias, const float* __restrict__ res,
    OutT* __restrict__ Cm, int M, int N, int K,
    const int* __restrict__ scat) {
    constexpr int GASZ = BMT * GAST;
    constexpr int MI = BMT / 64;
    constexpr int ALOAD = BMT / 32;
    extern __shared__ bf16 smem[];
    bf16* As = smem;
    bf16* Bs = smem + 3 * GASZ;

    int tid = threadIdx.x;
    int row0 = blockIdx.y * BMT, col0 = blockIdx.x * GBN;
    int wid = tid >> 5, lane = tid & 31;
    int wm = wid & 3, wn = wid >> 2;
    int g = lane >> 2, t = lane & 3;

    uint32_t sA0 = (uint32_t)__cvta_generic_to_shared(As);
    uint32_t sB0 = (uint32_t)__cvta_generic_to_shared(Bs);
    int ktiles = (K + GBK - 1) / GBK;

    auto load_tile = [&](int stage, int k0) {
        #pragma unroll
        for (int i = 0; i < ALOAD; i++) {
            int idx = tid + i * 256;
            int r = idx >> 3, kc = (idx & 7) << 3;
            bool ok = (k0 + kc) < K;
            cpasync16(sA0 + (uint32_t)((stage * GASZ + r * GAST + kc) * 2),
                      A + (long long)(row0 + r) * K + k0 + kc, ok);
        }
        #pragma unroll
        for (int i = 0; i < 4; i++) {
            int idx = tid + i * 256;
            int kk = idx >> 4, nc = (idx & 15) << 3;
            int gn = col0 + nc;
            bool ok = ((k0 + kk) < K) && (gn < N);
            cpasync16(sB0 + (uint32_t)((stage * GBSZ + kk * GBST + nc) * 2),
                      Bm + (long long)(k0 + kk) * N + gn, ok);
        }
    };

    float acc[MI][8][4];
    #pragma unroll
    for (int mi = 0; mi < MI; mi++)
        #pragma unroll
        for (int ni = 0; ni < 8; ni++)
            #pragma unroll
            for (int q = 0; q < 4; q++) acc[mi][ni][q] = 0.f;

    load_tile(0, 0);
    asm volatile("cp.async.commit_group;\n");
    load_tile(1, GBK);
    asm volatile("cp.async.commit_group;\n");

    for (int kt = 0; kt < ktiles; kt++) {
        asm volatile("cp.async.wait_group %0;\n" :: "n"(1));
        __syncthreads();
        if (kt + 2 < ktiles) load_tile((kt + 2) % 3, (kt + 2) * GBK);
        asm volatile("cp.async.commit_group;\n");

        uint32_t sAb = sA0 + (uint32_t)((kt % 3) * GASZ * 2);
        uint32_t sBb = sB0 + (uint32_t)((kt % 3) * GBSZ * 2);

        #pragma unroll
        for (int ks = 0; ks < 4; ks++) {
            uint32_t a[MI][4], b[8][2];
            #pragma unroll
            for (int mi = 0; mi < MI; mi++) {
                int row = wm * (BMT / 4) + mi * 16 + (lane & 15);
                uint32_t ad = sAb + (uint32_t)((row * GAST + ks * 16 + ((lane >> 4) << 3)) * 2);
                ldsm4(a[mi][0], a[mi][1], a[mi][2], a[mi][3], ad);
            }
            #pragma unroll
            for (int h = 0; h < 4; h++) {
                int rowk = ks * 16 + (lane & 7) + (((lane >> 3) & 1) << 3);
                int coln = wn * 64 + h * 16 + ((lane >> 4) << 3);
                uint32_t bd = sBb + (uint32_t)((rowk * GBST + coln) * 2);
                ldsm4t(b[2 * h][0], b[2 * h][1], b[2 * h + 1][0], b[2 * h + 1][1], bd);
            }
            #pragma unroll
            for (int mi = 0; mi < MI; mi++)
                #pragma unroll
                for (int ni = 0; ni < 8; ni++)
                    mma16816(acc[mi][ni], a[mi], b[ni]);
        }
    }

    #pragma unroll
    for (int mi = 0; mi < MI; mi++) {
        int r = row0 + wm * (BMT / 4) + mi * 16 + g;
        int ra = scat ? __ldg(scat + r) : r;
        int rb = scat ? __ldg(scat + r + 8) : r + 8;
        #pragma unroll
        for (int ni = 0; ni < 8; ni++) {
            int cidx = col0 + wn * 64 + ni * 8 + 2 * t;
            if (cidx < N) {
                float b0 = bias ? bias[cidx] : 0.f;
                float b1 = bias ? bias[cidx + 1] : 0.f;
                float x0 = acc[mi][ni][0] + b0, x1 = acc[mi][ni][1] + b1;
                float x2 = acc[mi][ni][2] + b0, x3 = acc[mi][ni][3] + b1;
                long long i0 = (long long)ra * N + cidx;
                long long i1 = (long long)rb * N + cidx;
                if (res) {
                    float2 r0 = *(const float2*)(res + i0);
                    float2 r1 = *(const float2*)(res + i1);
                    x0 += r0.x; x1 += r0.y; x2 += r1.x; x3 += r1.y;
                }
                store2(Cm + i0, x0, x1);
                store2(Cm + i1, x2, x3);
            }
        }
    }
}

// ---------------- T2T fold (gather form, bf16 in) + normalize ----------------
__global__ __launch_bounds__(256) void t2tfold_k(const bf16* __restrict__ h1,
                                                 float* __restrict__ I) {
    int idx = blockIdx.x * 256 + threadIdx.x;
    if (idx >= 16 * 40 * 60 * 108) return;
    int x = idx % 108;
    int y = (idx / 108) % 60;
    int c40 = (idx / (108 * 60)) % 40;
    int g = idx / (108 * 60 * 40);
    int pys[3], kis[3], pxs[3], kjs[3];
    int cy = 0, cx = 0;
    #pragma unroll
    for (int dp = 0; dp < 3; dp++) {
        int py = (y + 3) / 3 - dp;
        int ki = y + 3 - 3 * py;
        if (py >= 0 && py < 20 && ki < 7) { pys[cy] = py; kis[cy] = ki; cy++; }
        int px = (x + 3) / 3 - dp;
        int kj = x + 3 - 3 * px;
        if (px >= 0 && px < 36 && kj < 7) { pxs[cx] = px; kjs[cx] = kj; cx++; }
    }
    float s = 0.f;
    for (int a = 0; a < cy; a++)
        for (int bb = 0; bb < cx; bb++) {
            long long r = (long long)g * 720 + pys[a] * 36 + pxs[bb];
            s += __bfloat162float(h1[r * 1960 + c40 * 49 + kis[a] * 7 + kjs[bb]]);
        }
    I[idx] = s / (float)(cy * cx);
}

// ---------------- T2T unfold + exact GELU (paired bf162 out) ----------------
__global__ __launch_bounds__(256) void t2tunf_k(const float* __restrict__ I,
                                                bf16* __restrict__ h2) {
    int idx2 = blockIdx.x * 256 + threadIdx.x;
    if (idx2 >= TOK * FFN / 2) return;
    float vv[2];
    #pragma unroll
    for (int e = 0; e < 2; e++) {
        int idx = 2 * idx2 + e;
        int c = idx % 1960;
        int r = idx / 1960;
        int g = r / 720;
        int p = r - g * 720;
        int py = p / 36, px = p - py * 36;
        int c40 = c / 49;
        int kk = c - c40 * 49;
        int ki = kk / 7, kj = kk - ki * 7;
        int y = py * 3 + ki - 3, x = px * 3 + kj - 3;
        float v = 0.f;
        if (y >= 0 && y < 60 && x >= 0 && x < 108)
            v = I[(((long long)g * 40 + c40) * 60 + y) * 108 + x];
        vv[e] = 0.5f * v * (1.f + erff(v * 0.7071067811865475f));
    }
    ((bf162*)h2)[idx2] = __floats2bfloat162_rn(vv[0], vv[1]);
}

// ---------------- host launch ----------------
#define SYM(T, p, s) T* p; do { void* _t = nullptr; cudaGetSymbolAddress(&_t, s); (p) = (T*)_t; } while (0)

template <typename OutT, int BMT>
static void run_tgemm(const bf16* A, const bf16* Bm, const float* bias,
                      const float* res, OutT* C, int M, int N, int K,
                      const int* scat = nullptr) {
    dim3 grid((N + GBN - 1) / GBN, M / BMT);
    size_t sm = (size_t)3 * (BMT * GAST + GBSZ) * sizeof(bf16);
    cudaFuncSetAttribute(tgemm_k<OutT, BMT>, cudaFuncAttributeMaxDynamicSharedMemorySize, (int)sm);
    tgemm_k<OutT, BMT><<<grid, 256, sm>>>(A, Bm, bias, res, C, M, N, K, scat);
}

extern "C" void kernel_launch(void* const* d_in, const int* in_sizes, int n_in,
                              void* d_out, int out_size) {
    const float* x     = (const float*)d_in[0];
    const float* g1    = (const float*)d_in[1];
    const float* be1   = (const float*)d_in[2];
    const float* wqkv  = (const float*)d_in[3];
    const float* bqkv  = (const float*)d_in[4];
    const float* wproj = (const float*)d_in[5];
    const float* bproj = (const float*)d_in[6];
    const float* wpool = (const float*)d_in[7];
    const float* bpool = (const float*)d_in[8];
    const float* g2    = (const float*)d_in[9];
    const float* be2   = (const float*)d_in[10];
    const float* w1    = (const float*)d_in[11];
    const float* bf1   = (const float*)d_in[12];
    const float* w2    = (const float*)d_in[13];
    const float* bf2   = (const float*)d_in[14];
    float* out = (float*)d_out;

    SYM(bf16, xn, g_xn); SYM(bf16, qkv, g_qkv); SYM(bf16, Aw, g_Aw);
    SYM(float, xres, g_xres); SYM(bf16, hb, g_hb); SYM(float, I, g_I);
    SYM(int, qidx, g_qidx); SYM(int, kidx, g_kidx);
    SYM(bf16, wb, g_wb);
    bf16* wqkvb  = wb;
    bf16* wprojb = wb + WO_PROJ;
    bf16* w1b    = wb + WO_W1;
    bf16* w2b    = wb + WO_W2;

    initvalid_k<<<1, 32>>>();
    idx_k<<<(NWIN * NKP + 255) / 256, 256>>>(qidx, kidx);
    convw_all<<<(WTOT / 4 + 255) / 256, 256>>>(wqkv, wproj, w1, w2, wb);

    ln_k<<<TOK / 8, 256>>>(x, g1, be1, xn);
    pool_k<<<256, 128>>>(xn, wpool, bpool, xn + (long long)TOK * 512);
    run_tgemm<bf16, 128>(xn, wqkvb, bqkv, nullptr, qkv, MTOT, 1536, 512);

    {
        size_t smfa = (size_t)4 * FA_KT * FA_ST * sizeof(bf16);
        cudaFuncSetAttribute(fattn_k, cudaFuncAttributeMaxDynamicSharedMemorySize, (int)smfa);
        fattn_k<<<dim3(3, 128), 256, smfa>>>(qkv, qidx, kidx, Aw);
    }

    run_tgemm<float, 64>(Aw, wprojb, bproj, x, xres, TOK, 512, 512, qidx);
    ln_k<<<TOK / 8, 256>>>(xres, g2, be2, xn);
    run_tgemm<bf16, 128>(xn, w1b, bf1, nullptr, hb, TOK, FFN, 512);
    t2tfold_k<<<(16 * 40 * 60 * 108 + 255) / 256, 256>>>(hb, I);
    t2tunf_k<<<(TOK * FFN / 2 + 255) / 256, 256>>>(I, hb);
    run_tgemm<float, 64>(hb, w2b, bf2, xres, out, TOK, 512, FFN);
}